// round 5
// baseline (speedup 1.0000x reference)
#include <cuda_runtime.h>

// Fixed shapes: x = (4,64,256,256) f32, stoken = 16
#define Bn 4
#define Cc 64
#define NH 16      // superpixel grid 16x16
#define NS 256     // nH*nW
#define PP 65536   // H*W

typedef unsigned long long ull;

// Scratch (allocation-free: __device__ globals)
__device__ float g_cent[Bn * NS * Cc];
__device__ float g_num [Bn * NS * Cc];
__device__ float g_den [Bn * NS];

__device__ __forceinline__ void ffma2(ull& acc, ull a, ull b) {
    asm("fma.rn.f32x2 %0, %1, %2, %0;" : "+l"(acc) : "l"(a), "l"(b));
}
__device__ __forceinline__ ull pack2(float x, float y) {
    ull r; asm("mov.b64 %0, {%1, %2};" : "=l"(r) : "f"(x), "f"(y)); return r;
}
__device__ __forceinline__ float2 unpack2(ull v) {
    float2 r; asm("mov.b64 {%0, %1}, %2;" : "=f"(r.x), "=f"(r.y) : "l"(v)); return r;
}

// ---------------------------------------------------------------------------
// Zero-fill: SMALL grid (grid-stride over planes), low-priority stream, so it
// saturates DRAM writes while the compute chain co-runs on the remaining SM
// slots. Skips float4s inside each plane's 3x3 affinity region (disjoint 64B
// chunks written by pass 1 — no ordering needed).
// ---------------------------------------------------------------------------
#define FILL_CTAS 296
__global__ __launch_bounds__(256) void zero_fill_kernel(float4* __restrict__ A) {
    int t = threadIdx.x;
    const float4 z = make_float4(0.f, 0.f, 0.f, 0.f);
    for (int plane_id = blockIdx.x; plane_id < Bn * NS; plane_id += FILL_CTAS) {
        int s = plane_id & 255;
        int si = s >> 4, sj = s & 15;
        float4* plane = A + ((size_t)plane_id << 14);   // 16384 float4 per plane
        #pragma unroll 8
        for (int i = 0; i < 64; i++) {
            int e4 = i * 256 + t;
            int p = e4 << 2;
            int bi = p >> 12;
            int bj = (p >> 4) & 15;
            int di = si - bi + 1, dj = sj - bj + 1;
            if ((unsigned)di > 2u || (unsigned)dj > 2u)
                __stcs(&plane[e4], z);
        }
    }
}

// ---------------------------------------------------------------------------
// Initial centroids: block mean over each 16x16 block. Also zeroes scratch.
// ---------------------------------------------------------------------------
__global__ __launch_bounds__(256) void init_cent_kernel(const float* __restrict__ x) {
    int b = blockIdx.y, s = blockIdx.x;
    int bi = s >> 4, bj = s & 15;
    int tid = threadIdx.x;
    int c = tid >> 2, q = tid & 3;
    int base = ((bi * 16) << 8) + bj * 16;
    const float4* fc = (const float4*)(x + (((size_t)b * Cc + c) << 16) + base);
    float4 s4 = make_float4(0.f, 0.f, 0.f, 0.f);
    #pragma unroll 4
    for (int t = 0; t < 16; t++) {
        int j = q + t * 4;                 // float4 index within block
        float4 v = fc[(j >> 2) * 64 + (j & 3)];
        s4.x += v.x; s4.y += v.y; s4.z += v.z; s4.w += v.w;
    }
    float acc = (s4.x + s4.y) + (s4.z + s4.w);
    __shared__ float part[256];
    part[tid] = acc;
    __syncthreads();
    if (tid < 64) {
        int o4 = tid * 4;
        float v = (part[o4] + part[o4 + 1]) + (part[o4 + 2] + part[o4 + 3]);
        int idx = (b * NS + s) * Cc + tid;
        g_cent[idx] = v * (1.f / 256.f);
        g_num[idx]  = 0.f;
    }
    if (tid == 64) g_den[b * NS + s] = 0.f;
}

// ---------------------------------------------------------------------------
// Affinity pass. One CTA per (b, 16x16 pixel block); 256 threads = 256 pixels.
// cent_sm holds s = -2*cent so the dot loop needs no epilogue scaling:
//   dist = f2 + 0.25*sum(s^2) + sum(f*s)
// PASS 0: centroids from g_cent; fused num/den reduction with global atomics.
// PASS 1: centroids from g_num/g_den (fused finalize); scatters into A.
// ---------------------------------------------------------------------------
template <int PASS>
__global__ __launch_bounds__(256) void affinity_kernel(const float* __restrict__ x,
                                                       float* __restrict__ A) {
    int b = blockIdx.y, sblk = blockIdx.x;
    int bi = sblk >> 4, bj = sblk & 15;
    int tid = threadIdx.x;

    __shared__ __align__(16) float cent_sm[9][64];   // -2 * centroid
    __shared__ __align__(16) float aff_sm[9][256];
    __shared__ float c2_sm[9];
    __shared__ float den_sm[9];
    __shared__ int   cand_s[9];
    __shared__ int   cand_v[9];

    if (tid < 9) {
        int ci = bi + tid / 3 - 1, cj = bj + tid % 3 - 1;
        int v = (ci >= 0 && ci < NH && cj >= 0 && cj < NH);
        cand_v[tid] = v;
        int s = v ? ci * NH + cj : 0;
        cand_s[tid] = s;
        if (PASS == 1) den_sm[tid] = g_den[b * NS + s] + 1e-16f;
    }
    __syncthreads();
    for (int i = tid; i < 9 * 64; i += 256) {
        int k = i >> 6, c = i & 63;
        int gi = (b * NS + cand_s[k]) * Cc + c;
        float cv = (PASS == 0) ? g_cent[gi] : g_num[gi] / den_sm[k];
        cent_sm[k][c] = -2.f * cv;
    }
    __syncthreads();
    if (tid < 9) {
        float s2 = 0.f;
        #pragma unroll 8
        for (int c = 0; c < 64; c++) { float v = cent_sm[tid][c]; s2 += v * v; }
        c2_sm[tid] = 0.25f * s2;          // sum(cent^2)
    }
    __syncthreads();

    // ---- per-pixel: 9 candidates x 64 channels, f32x2 FMA, LDS.128->ull2 ----
    int ly = tid >> 4, lx = tid & 15;
    int p = ((bi * 16 + ly) << 8) + bj * 16 + lx;
    const float* fb = x + (((size_t)b * Cc) << 16) + p;
    ull dacc[9];
    #pragma unroll
    for (int k = 0; k < 9; k++) dacc[k] = 0ull;
    ull facc = 0ull;
    #pragma unroll
    for (int c = 0; c < 64; c += 8) {
        float f[8];
        #pragma unroll
        for (int j = 0; j < 8; j++) f[j] = fb[(size_t)(c + j) << 16];
        ull fp0 = pack2(f[0], f[1]), fp1 = pack2(f[2], f[3]);
        ull fp2 = pack2(f[4], f[5]), fp3 = pack2(f[6], f[7]);
        ffma2(facc, fp0, fp0); ffma2(facc, fp1, fp1);
        ffma2(facc, fp2, fp2); ffma2(facc, fp3, fp3);
        #pragma unroll
        for (int k = 0; k < 9; k++) {
            ulonglong2 cv0 = *(const ulonglong2*)&cent_sm[k][c];
            ulonglong2 cv1 = *(const ulonglong2*)&cent_sm[k][c + 4];
            ffma2(dacc[k], fp0, cv0.x); ffma2(dacc[k], fp1, cv0.y);
            ffma2(dacc[k], fp2, cv1.x); ffma2(dacc[k], fp3, cv1.y);
        }
    }
    float2 fh = unpack2(facc);
    float f2 = fh.x + fh.y;

    // ---- masked softmax over 9 candidates ----
    float aff[9];
    float mx = -3.0e38f;
    #pragma unroll
    for (int k = 0; k < 9; k++) {
        float2 dh = unpack2(dacc[k]);
        float d = f2 + c2_sm[k] + (dh.x + dh.y);
        aff[k] = cand_v[k] ? -d : -1e30f;
        mx = fmaxf(mx, aff[k]);
    }
    float ssum = 0.f;
    #pragma unroll
    for (int k = 0; k < 9; k++) { float e = __expf(aff[k] - mx); aff[k] = e; ssum += e; }
    float rs = 1.f / ssum;
    #pragma unroll
    for (int k = 0; k < 9; k++) aff[k] = cand_v[k] ? aff[k] * rs : 0.f;

    #pragma unroll
    for (int k = 0; k < 9; k++) aff_sm[k][tid] = aff[k];

    if (PASS == 0) {
        // den: warp reduce each of 9 affinities over the 256 pixels
        __shared__ float denpart[8][9];
        #pragma unroll
        for (int k = 0; k < 9; k++) {
            float v = aff[k];
            v += __shfl_xor_sync(0xffffffffu, v, 16);
            v += __shfl_xor_sync(0xffffffffu, v, 8);
            v += __shfl_xor_sync(0xffffffffu, v, 4);
            v += __shfl_xor_sync(0xffffffffu, v, 2);
            v += __shfl_xor_sync(0xffffffffu, v, 1);
            if ((tid & 31) == 0) denpart[tid >> 5][k] = v;
        }
        __syncthreads();

        // num[k][c] = sum_p aff[k][p] * feats[c][p]  (pixel-quad, LDS.128->ull2)
        int c = tid >> 2, g = tid & 3;
        const float* fc = x + (((size_t)b * Cc + c) << 16);
        int base = ((bi * 16) << 8) + bj * 16;
        ull acc2[9];
        #pragma unroll
        for (int k = 0; k < 9; k++) acc2[k] = 0ull;
        #pragma unroll 4
        for (int t = 0; t < 16; t++) {
            int j = g + t * 4;                        // pixel-quad index [0,64)
            int row = j >> 2, c4 = j & 3;
            int i = row * 16 + c4 * 4;                // local pixel base (16B aligned)
            float4 fq = *(const float4*)(fc + base + (row << 8) + c4 * 4);
            ull fp0 = pack2(fq.x, fq.y), fp1 = pack2(fq.z, fq.w);
            #pragma unroll
            for (int k = 0; k < 9; k++) {
                ulonglong2 aq = *(const ulonglong2*)&aff_sm[k][i];
                ffma2(acc2[k], fp0, aq.x);
                ffma2(acc2[k], fp1, aq.y);
            }
        }
        __shared__ float part[9][256];
        #pragma unroll
        for (int k = 0; k < 9; k++) {
            float2 h = unpack2(acc2[k]);
            part[k][tid] = h.x + h.y;
        }
        __syncthreads();

        for (int i = tid; i < 9 * 64; i += 256) {
            int k = i >> 6, c2i = i & 63;
            if (cand_v[k]) {
                int o4 = c2i * 4;
                float v = (part[k][o4] + part[k][o4 + 1]) + (part[k][o4 + 2] + part[k][o4 + 3]);
                atomicAdd(&g_num[(b * NS + cand_s[k]) * Cc + c2i], v);
            }
        }
        if (tid < 9 && cand_v[tid]) {
            float v = 0.f;
            #pragma unroll
            for (int w = 0; w < 8; w++) v += denpart[w][tid];
            atomicAdd(&g_den[b * NS + cand_s[tid]], v);
        }
    } else {
        // scatter into dense A with vectorized streaming stores
        __syncthreads();
        for (int i = tid; i < 9 * 64; i += 256) {
            int k = i >> 6, e4 = i & 63;
            if (cand_v[k]) {
                int row = e4 >> 2, c4 = e4 & 3;
                float4 v = *(const float4*)&aff_sm[k][row * 16 + c4 * 4];
                size_t off = (((size_t)(b * NS + cand_s[k])) << 16)
                           + (((bi * 16 + row) << 8) + bj * 16 + c4 * 4);
                __stcs((float4*)(A + off), v);
            }
        }
    }
}

extern "C" void kernel_launch(void* const* d_in, const int* in_sizes, int n_in,
                              void* d_out, int out_size) {
    const float* x = (const float*)d_in[0];
    float* A = (float*)d_out;

    static cudaStream_t s2 = nullptr;
    static cudaEvent_t ev0 = nullptr, ev1 = nullptr;
    if (!s2) {   // first call = correctness run (not captured): safe to create
        int least, greatest;
        cudaDeviceGetStreamPriorityRange(&least, &greatest);
        cudaStreamCreateWithPriority(&s2, cudaStreamNonBlocking, least);  // lowest prio
        cudaEventCreateWithFlags(&ev0, cudaEventDisableTiming);
        cudaEventCreateWithFlags(&ev1, cudaEventDisableTiming);
    }

    dim3 grid(NS, Bn);

    // Fork: low-priority, small-footprint zero-fill co-runs with the chain.
    cudaEventRecord(ev0, 0);
    cudaStreamWaitEvent(s2, ev0, 0);
    zero_fill_kernel<<<FILL_CTAS, 256, 0, s2>>>((float4*)A);
    cudaEventRecord(ev1, s2);

    // Compute chain on the capture stream (shares SMs with the fill).
    init_cent_kernel<<<grid, 256>>>(x);
    affinity_kernel<0><<<grid, 256>>>(x, A);
    affinity_kernel<1><<<grid, 256>>>(x, A);

    // Join (required for valid capture; no data ordering needed — disjoint bytes).
    cudaStreamWaitEvent(0, ev1, 0);
}

// round 6
// speedup vs baseline: 1.3597x; 1.3597x over previous
#include <cuda_runtime.h>

// Fixed shapes: x = (4,64,256,256) f32, stoken = 16
#define Bn 4
#define Cc 64
#define NH 16      // superpixel grid 16x16
#define NS 256     // nH*nW
#define PP 65536   // H*W

typedef unsigned long long ull;

// Scratch (allocation-free: __device__ globals)
__device__ float g_cent[Bn * NS * Cc];
__device__ float g_num [Bn * NS * Cc];
__device__ float g_den [Bn * NS];

__device__ __forceinline__ void ffma2(ull& acc, ull a, ull b) {
    asm("fma.rn.f32x2 %0, %1, %2, %0;" : "+l"(acc) : "l"(a), "l"(b));
}
__device__ __forceinline__ ull pack2(float x, float y) {
    ull r; asm("mov.b64 %0, {%1, %2};" : "=l"(r) : "f"(x), "f"(y)); return r;
}
__device__ __forceinline__ float2 unpack2(ull v) {
    float2 r; asm("mov.b64 {%0, %1}, %2;" : "=f"(r.x), "=f"(r.y) : "l"(v)); return r;
}

// ---------------------------------------------------------------------------
// Inline zero-fill of a slice [lo,hi) of plane (b,s), skipping float4s inside
// the plane's 3x3 affinity region (those are written by pass 1's scatter —
// byte-disjoint, so no ordering is needed). Fire-and-forget streaming stores
// that drain while the caller's compute stalls on load latency.
// ---------------------------------------------------------------------------
__device__ __forceinline__ void fill_slice(float4* __restrict__ A, int b, int s,
                                           int lo, int hi, int tid) {
    int si = s >> 4, sj = s & 15;
    float4* plane = A + ((size_t)(b * NS + s) << 14);   // 16384 float4 per plane
    const float4 z = make_float4(0.f, 0.f, 0.f, 0.f);
    #pragma unroll 4
    for (int e4 = lo + tid; e4 < hi; e4 += 256) {
        int p = e4 << 2;
        int bi = p >> 12;
        int bj = (p >> 4) & 15;
        int di = si - bi + 1, dj = sj - bj + 1;
        if ((unsigned)di > 2u || (unsigned)dj > 2u)
            __stcs(&plane[e4], z);
    }
}

// Fill split across the three chain kernels (16384 float4 per plane total).
#define FILL_INIT_END 3584
#define FILL_P0_END   9984

// ---------------------------------------------------------------------------
// Initial centroids: block mean over each 16x16 block. Also zeroes scratch
// and fills its plane slice [0, FILL_INIT_END).
// ---------------------------------------------------------------------------
__global__ __launch_bounds__(256) void init_cent_kernel(const float* __restrict__ x,
                                                        float4* __restrict__ A) {
    int b = blockIdx.y, s = blockIdx.x;
    int bi = s >> 4, bj = s & 15;
    int tid = threadIdx.x;

    fill_slice(A, b, s, 0, FILL_INIT_END, tid);

    int c = tid >> 2, q = tid & 3;
    int base = ((bi * 16) << 8) + bj * 16;
    const float4* fc = (const float4*)(x + (((size_t)b * Cc + c) << 16) + base);
    float4 s4 = make_float4(0.f, 0.f, 0.f, 0.f);
    #pragma unroll 4
    for (int t = 0; t < 16; t++) {
        int j = q + t * 4;                 // float4 index within block
        float4 v = fc[(j >> 2) * 64 + (j & 3)];
        s4.x += v.x; s4.y += v.y; s4.z += v.z; s4.w += v.w;
    }
    float acc = (s4.x + s4.y) + (s4.z + s4.w);
    __shared__ float part[256];
    part[tid] = acc;
    __syncthreads();
    if (tid < 64) {
        int o4 = tid * 4;
        float v = (part[o4] + part[o4 + 1]) + (part[o4 + 2] + part[o4 + 3]);
        int idx = (b * NS + s) * Cc + tid;
        g_cent[idx] = v * (1.f / 256.f);
        g_num[idx]  = 0.f;
    }
    if (tid == 64) g_den[b * NS + s] = 0.f;
}

// ---------------------------------------------------------------------------
// Affinity pass. One CTA per (b, 16x16 pixel block); 256 threads = 256 pixels.
// cent_sm holds t = -2*cent:  dist = f2 + 0.25*sum(t^2) + sum(f*t).
// PASS 0: centroids from g_cent; fused num/den reduction; fills [3584,9984).
// PASS 1: centroids from g_num/g_den; scatters into A; fills [9984,16384).
// ---------------------------------------------------------------------------
template <int PASS>
__global__ __launch_bounds__(256) void affinity_kernel(const float* __restrict__ x,
                                                       float* __restrict__ A) {
    int b = blockIdx.y, sblk = blockIdx.x;
    int bi = sblk >> 4, bj = sblk & 15;
    int tid = threadIdx.x;

    __shared__ __align__(16) float cent_sm[9][64];   // -2 * centroid
    __shared__ __align__(16) float aff_sm[9][256];
    __shared__ float c2_sm[9];
    __shared__ float den_sm[9];
    __shared__ int   cand_s[9];
    __shared__ int   cand_v[9];

    if (tid < 9) {
        int ci = bi + tid / 3 - 1, cj = bj + tid % 3 - 1;
        int v = (ci >= 0 && ci < NH && cj >= 0 && cj < NH);
        cand_v[tid] = v;
        int s = v ? ci * NH + cj : 0;
        cand_s[tid] = s;
        if (PASS == 1) den_sm[tid] = g_den[b * NS + s] + 1e-16f;
    }

    // streamed zero-fill of this CTA's plane slice (overlaps with compute)
    if (PASS == 0) fill_slice((float4*)A, b, sblk, FILL_INIT_END, FILL_P0_END, tid);
    else           fill_slice((float4*)A, b, sblk, FILL_P0_END, 16384, tid);

    __syncthreads();
    for (int i = tid; i < 9 * 64; i += 256) {
        int k = i >> 6, c = i & 63;
        int gi = (b * NS + cand_s[k]) * Cc + c;
        float cv = (PASS == 0) ? g_cent[gi] : g_num[gi] / den_sm[k];
        cent_sm[k][c] = -2.f * cv;
    }
    __syncthreads();
    if (tid < 9) {
        float s2 = 0.f;
        #pragma unroll 8
        for (int c = 0; c < 64; c++) { float v = cent_sm[tid][c]; s2 += v * v; }
        c2_sm[tid] = 0.25f * s2;          // sum(cent^2)
    }
    __syncthreads();

    // ---- per-pixel dots: 9 candidates x 64 channels, packed f32x2 FMA ----
    int ly = tid >> 4, lx = tid & 15;
    int p = ((bi * 16 + ly) << 8) + bj * 16 + lx;
    const float* fb = x + (((size_t)b * Cc) << 16) + p;
    ull dacc[9];
    #pragma unroll
    for (int k = 0; k < 9; k++) dacc[k] = 0ull;
    ull facc = 0ull;
    #pragma unroll 4
    for (int c = 0; c < 64; c += 4) {
        float f0 = fb[(size_t)(c + 0) << 16];
        float f1 = fb[(size_t)(c + 1) << 16];
        float f2v = fb[(size_t)(c + 2) << 16];
        float f3 = fb[(size_t)(c + 3) << 16];
        ull fp0 = pack2(f0, f1), fp1 = pack2(f2v, f3);
        ffma2(facc, fp0, fp0);
        ffma2(facc, fp1, fp1);
        #pragma unroll
        for (int k = 0; k < 9; k++) {
            float4 cv = *(const float4*)&cent_sm[k][c];
            ffma2(dacc[k], fp0, pack2(cv.x, cv.y));
            ffma2(dacc[k], fp1, pack2(cv.z, cv.w));
        }
    }
    float2 fh = unpack2(facc);
    float f2 = fh.x + fh.y;

    // ---- masked softmax over 9 candidates ----
    float aff[9];
    float mx = -3.0e38f;
    #pragma unroll
    for (int k = 0; k < 9; k++) {
        float2 dh = unpack2(dacc[k]);
        float d = f2 + c2_sm[k] + (dh.x + dh.y);
        aff[k] = cand_v[k] ? -d : -1e30f;
        mx = fmaxf(mx, aff[k]);
    }
    float ssum = 0.f;
    #pragma unroll
    for (int k = 0; k < 9; k++) { float e = __expf(aff[k] - mx); aff[k] = e; ssum += e; }
    float rs = 1.f / ssum;
    #pragma unroll
    for (int k = 0; k < 9; k++) aff[k] = cand_v[k] ? aff[k] * rs : 0.f;

    #pragma unroll
    for (int k = 0; k < 9; k++) aff_sm[k][tid] = aff[k];

    if (PASS == 0) {
        // den: warp reduce each of 9 affinities over the 256 pixels
        __shared__ float denpart[8][9];
        #pragma unroll
        for (int k = 0; k < 9; k++) {
            float v = aff[k];
            v += __shfl_xor_sync(0xffffffffu, v, 16);
            v += __shfl_xor_sync(0xffffffffu, v, 8);
            v += __shfl_xor_sync(0xffffffffu, v, 4);
            v += __shfl_xor_sync(0xffffffffu, v, 2);
            v += __shfl_xor_sync(0xffffffffu, v, 1);
            if ((tid & 31) == 0) denpart[tid >> 5][k] = v;
        }
        __syncthreads();

        // num[k][c] = sum_p aff[k][p] * feats[c][p]  (pixel-quad, LDG.128)
        int c = tid >> 2, g = tid & 3;
        const float* fc = x + (((size_t)b * Cc + c) << 16);
        int base = ((bi * 16) << 8) + bj * 16;
        ull acc2[9];
        #pragma unroll
        for (int k = 0; k < 9; k++) acc2[k] = 0ull;
        #pragma unroll 4
        for (int t = 0; t < 16; t++) {
            int j = g + t * 4;                        // pixel-quad index [0,64)
            int row = j >> 2, c4 = j & 3;
            int i = row * 16 + c4 * 4;                // local pixel base
            float4 fq = *(const float4*)(fc + base + (row << 8) + c4 * 4);
            ull fp0 = pack2(fq.x, fq.y), fp1 = pack2(fq.z, fq.w);
            #pragma unroll
            for (int k = 0; k < 9; k++) {
                float4 aq = *(const float4*)&aff_sm[k][i];
                ffma2(acc2[k], fp0, pack2(aq.x, aq.y));
                ffma2(acc2[k], fp1, pack2(aq.z, aq.w));
            }
        }
        __shared__ float part[9][256];
        #pragma unroll
        for (int k = 0; k < 9; k++) {
            float2 h = unpack2(acc2[k]);
            part[k][tid] = h.x + h.y;
        }
        __syncthreads();

        for (int i = tid; i < 9 * 64; i += 256) {
            int k = i >> 6, c2i = i & 63;
            if (cand_v[k]) {
                int o4 = c2i * 4;
                float v = (part[k][o4] + part[k][o4 + 1]) + (part[k][o4 + 2] + part[k][o4 + 3]);
                atomicAdd(&g_num[(b * NS + cand_s[k]) * Cc + c2i], v);
            }
        }
        if (tid < 9 && cand_v[tid]) {
            float v = 0.f;
            #pragma unroll
            for (int w = 0; w < 8; w++) v += denpart[w][tid];
            atomicAdd(&g_den[b * NS + cand_s[tid]], v);
        }
    } else {
        // scatter into dense A with vectorized streaming stores
        __syncthreads();
        for (int i = tid; i < 9 * 64; i += 256) {
            int k = i >> 6, e4 = i & 63;
            if (cand_v[k]) {
                int row = e4 >> 2, c4 = e4 & 3;
                float4 v = *(const float4*)&aff_sm[k][row * 16 + c4 * 4];
                size_t off = (((size_t)(b * NS + cand_s[k])) << 16)
                           + (((bi * 16 + row) << 8) + bj * 16 + c4 * 4);
                __stcs((float4*)(A + off), v);
            }
        }
    }
}

extern "C" void kernel_launch(void* const* d_in, const int* in_sizes, int n_in,
                              void* d_out, int out_size) {
    const float* x = (const float*)d_in[0];
    float* A = (float*)d_out;

    dim3 grid(NS, Bn);
    // Single stream; zero-fill is folded into each kernel as streaming stores.
    init_cent_kernel<<<grid, 256>>>(x, (float4*)A);
    affinity_kernel<0><<<grid, 256>>>(x, A);
    affinity_kernel<1><<<grid, 256>>>(x, A);
}